// round 5
// baseline (speedup 1.0000x reference)
#include <cuda_runtime.h>
#include <stdint.h>

// Problem constants (from reference): N=50000, IN_CH=256, OUT_CH=128, NNZ=800000
#define OUT_CH 128
#define MAX_N 50000

// Scratch: filtered [N,128] and tmp [N,128] as device globals (no allocation).
// Declared as float4 so the base is 16B-aligned (required by red.global.add.v4).
__device__ float4 g_filtered[MAX_N * OUT_CH / 4];
__device__ float4 g_tmp[MAX_N * OUT_CH / 4];

// Zero three float4 buffers (grid-stride).
__global__ void zero3_kernel(float4* __restrict__ a, float4* __restrict__ b,
                             float4* __restrict__ c, int n4) {
    int i = blockIdx.x * blockDim.x + threadIdx.x;
    int stride = gridDim.x * blockDim.x;
    float4 z = make_float4(0.f, 0.f, 0.f, 0.f);
    for (; i < n4; i += stride) {
        a[i] = z;
        b[i] = z;
        c[i] = z;
    }
}

// COO SpMM: out[row,:] += val * (USE_THETA ? theta[col] : 1) * dense[col,:]
// One warp per nonzero; each lane handles 4 columns (float4), scatter via
// vectorized red.global.add.v4.f32 (sm_90+).
template <bool USE_THETA>
__global__ void __launch_bounds__(256)
spmm_coo_kernel(const int* __restrict__ rows,
                const int* __restrict__ cols,
                const float* __restrict__ vals,
                const float* __restrict__ theta,
                const float* __restrict__ dense,
                float* __restrict__ out,
                int nnz) {
    int warp = blockIdx.x * (blockDim.x >> 5) + (threadIdx.x >> 5);
    if (warp >= nnz) return;
    int lane = threadIdx.x & 31;

    int r = __ldg(&rows[warp]);
    int c = __ldg(&cols[warp]);
    float v = __ldg(&vals[warp]);
    if (USE_THETA) v *= __ldg(&theta[c]);

    const float4* __restrict__ drow =
        reinterpret_cast<const float4*>(dense + (size_t)c * OUT_CH);
    float4 d = __ldg(&drow[lane]);

    float4 contrib = make_float4(v * d.x, v * d.y, v * d.z, v * d.w);
    float* o = out + (size_t)r * OUT_CH + lane * 4;

    asm volatile("red.global.add.v4.f32 [%0], {%1, %2, %3, %4};"
                 :: "l"(o), "f"(contrib.x), "f"(contrib.y),
                    "f"(contrib.z), "f"(contrib.w)
                 : "memory");
}

// In-place ReLU.
__global__ void relu_kernel(float* __restrict__ x, int n) {
    int i = blockIdx.x * blockDim.x + threadIdx.x;
    int stride = gridDim.x * blockDim.x;
    for (; i < n; i += stride) {
        float v = x[i];
        x[i] = v > 0.f ? v : 0.f;
    }
}

extern "C" void kernel_launch(void* const* d_in, const int* in_sizes, int n_in,
                              void* d_out, int out_size) {
    // Input order (metadata): phi_indices, phi_values, phi_inverse_indices,
    // phi_inverse_values, feature_indices, feature_values, weight_matrix,
    // diagonal_weight_filter, dropout
    const int*   phi_idx   = (const int*)d_in[0];      // [2, nnz_phi]
    const float* phi_vals  = (const float*)d_in[1];
    const int*   phii_idx  = (const int*)d_in[2];      // [2, nnz_phii]
    const float* phii_vals = (const float*)d_in[3];
    const int*   feat_idx  = (const int*)d_in[4];      // [2, nnz_feat]
    const float* feat_vals = (const float*)d_in[5];
    const float* weight    = (const float*)d_in[6];    // [IN_CH, 128]
    const float* theta     = (const float*)d_in[7];    // [N]

    int nnz_phi  = in_sizes[1];
    int nnz_phii = in_sizes[3];
    int nnz_feat = in_sizes[5];
    int n_nodes  = in_sizes[7];
    (void)n_in;

    float* out = (float*)d_out;
    float* filtered;
    float* tmp;
    cudaGetSymbolAddress((void**)&filtered, g_filtered);
    cudaGetSymbolAddress((void**)&tmp, g_tmp);

    // 1) Zero scratch + output (output is poisoned by the harness).
    int n4 = (n_nodes * OUT_CH) / 4;
    {
        int threads = 256;
        int blocks = 1184;  // 148 SMs * 8
        zero3_kernel<<<blocks, threads>>>((float4*)filtered, (float4*)tmp,
                                          (float4*)out, n4);
    }

    const int THREADS = 256;
    const int WARPS_PER_BLOCK = THREADS / 32;

    // 2) filtered = feature_coo @ W   (rows=node, cols=feature-channel)
    {
        int blocks = (nnz_feat + WARPS_PER_BLOCK - 1) / WARPS_PER_BLOCK;
        spmm_coo_kernel<false><<<blocks, THREADS>>>(
            feat_idx, feat_idx + nnz_feat, feat_vals,
            nullptr, weight, filtered, nnz_feat);
    }

    // 3) tmp = phi_inv @ filtered
    {
        int blocks = (nnz_phii + WARPS_PER_BLOCK - 1) / WARPS_PER_BLOCK;
        spmm_coo_kernel<false><<<blocks, THREADS>>>(
            phii_idx, phii_idx + nnz_phii, phii_vals,
            nullptr, filtered, tmp, nnz_phii);
    }

    // 4) out = (phi * diag(theta)) @ tmp  (theta indexed by phi column)
    {
        int blocks = (nnz_phi + WARPS_PER_BLOCK - 1) / WARPS_PER_BLOCK;
        spmm_coo_kernel<true><<<blocks, THREADS>>>(
            phi_idx, phi_idx + nnz_phi, phi_vals,
            theta, tmp, out, nnz_phi);
    }

    // 5) ReLU in place on out.
    {
        int threads = 256;
        int blocks = 1184;
        relu_kernel<<<blocks, threads>>>(out, out_size);
    }
}